// round 14
// baseline (speedup 1.0000x reference)
#include <cuda_runtime.h>
#include <cuda_fp16.h>
#include <cstdint>

#define BB 2
#define NN 2048
#define DD 64
#define TI 128
#define TJ 64

// ---------------- smem layout ----------------
#define OFF_XN      0                     // 128 floats
#define OFF_YN      512                   // 64 floats
#define OFF_PX      1024                  // 2048 float partials (x)
#define OFF_PY      (OFF_PX + 8192)       // 1024 float partials (y)
#define OFF_AXH     (OFF_PY + 4096)       // 13312: x tile 128 rows x 128B
#define OFF_BYH     (OFF_AXH + 128 * 128) // y tile 64 rows x 128B
#define SMEM_BYTES  (OFF_BYH + 64 * 128)  // 37888

__device__ __forceinline__ uint32_t smem_u32(const void* p) {
    uint32_t a;
    asm("{ .reg .u64 t; cvta.to.shared.u64 t, %1; cvt.u32.u64 %0, t; }" : "=r"(a) : "l"(p));
    return a;
}
#define SW128(off) ((off) ^ (((off) >> 3) & 0x70))

__device__ __forceinline__ void ldsm4(uint32_t* r, uint32_t addr) {
    asm volatile("ldmatrix.sync.aligned.m8n8.x4.shared.b16 {%0,%1,%2,%3}, [%4];"
        : "=r"(r[0]), "=r"(r[1]), "=r"(r[2]), "=r"(r[3]) : "r"(addr));
}

__device__ __forceinline__ void mma16816(float* c, const uint32_t* a,
                                         uint32_t b0, uint32_t b1) {
    asm volatile("mma.sync.aligned.m16n8k16.row.col.f32.f16.f16.f32 "
        "{%0,%1,%2,%3}, {%4,%5,%6,%7}, {%8,%9}, {%0,%1,%2,%3};"
        : "+f"(c[0]), "+f"(c[1]), "+f"(c[2]), "+f"(c[3])
        : "r"(a[0]), "r"(a[1]), "r"(a[2]), "r"(a[3]), "r"(b0), "r"(b1));
}

// y-row permutation (within 16-row groups): thread's 4 acc values cover 4
// consecutive logical j -> STG.128 epilogue.
// j = q*16 + w*4 + h*2 + l  ->  p = q*16 + h*8 + w*2 + l
__device__ __forceinline__ int permute_row(int j) {
    return (j & ~15) | ((j & 2) << 2) | ((j & 12) >> 1) | (j & 1);
}

// ---------------------------------------------------------------------------
// 128x64 tile per CTA (occ 3). fp16 single-pass GEMM on HMMA, exact fp32
// norms; dist = xn + yn - 2*(xh . yh).
// ---------------------------------------------------------------------------
__global__ __launch_bounds__(256, 3)
void pd_kernel(const float* __restrict__ x, const float* __restrict__ y,
               float* __restrict__ out) {
    extern __shared__ char smem[];
    uint32_t sb = smem_u32(smem);
    int tid = threadIdx.x;
    int wid = tid >> 5;
    int lane = tid & 31;
    int b = blockIdx.z;
    int i0 = blockIdx.y * TI;
    int j0 = blockIdx.x * TJ;

    float* xns_sm = (float*)(smem + OFF_XN);
    float* yns_sm = (float*)(smem + OFF_YN);
    float* px = (float*)(smem + OFF_PX);
    float* py = (float*)(smem + OFF_PY);

    // ---- fill: LDG fp32 rows -> fp16 subtiles + per-float4 norm partials ----
    const float4* xg = (const float4*)(x + ((size_t)b * NN + i0) * DD);
    const float4* yg = (const float4*)(y + ((size_t)b * NN + j0) * DD);
    #pragma unroll
    for (int it = 0; it < 8; it++) {
        int idx = tid + it * 256;          // 2048 float4 = 128 rows x 16
        int row = idx >> 4;
        int k4 = (idx & 15) << 2;

        float4 v = xg[idx];
        px[idx] = v.x * v.x + v.y * v.y + v.z * v.z + v.w * v.w;
        __half2 h0 = __float22half2_rn(make_float2(v.x, v.y));
        __half2 h1 = __float22half2_rn(make_float2(v.z, v.w));
        uint32_t offx = SW128((uint32_t)(row * 128 + k4 * 2));
        *(uint2*)(smem + OFF_AXH + offx) = make_uint2(*(uint32_t*)&h0, *(uint32_t*)&h1);
    }
    #pragma unroll
    for (int it = 0; it < 4; it++) {
        int idx = tid + it * 256;          // 1024 float4 = 64 rows x 16
        int row = idx >> 4;
        int k4 = (idx & 15) << 2;

        float4 w = yg[idx];
        py[idx] = w.x * w.x + w.y * w.y + w.z * w.z + w.w * w.w;
        __half2 g0 = __float22half2_rn(make_float2(w.x, w.y));
        __half2 g1 = __float22half2_rn(make_float2(w.z, w.w));
        int prow = permute_row(row);
        uint32_t offy = SW128((uint32_t)(prow * 128 + k4 * 2));
        *(uint2*)(smem + OFF_BYH + offy) = make_uint2(*(uint32_t*)&g0, *(uint32_t*)&g1);
    }
    __syncthreads();

    // ---- norm reduction: thread t<128 -> x row t; t in [128,192) -> y row ----
    if (tid < 192) {
        const float4* p4 = (tid < 128) ? (const float4*)px : (const float4*)py;
        int r = (tid < 128) ? tid : tid - 128;
        float4 a0 = p4[r * 4 + 0], a1 = p4[r * 4 + 1];
        float4 a2 = p4[r * 4 + 2], a3 = p4[r * 4 + 3];
        float s = ((a0.x + a0.y) + (a0.z + a0.w)) + ((a1.x + a1.y) + (a1.z + a1.w))
                + ((a2.x + a2.y) + (a2.z + a2.w)) + ((a3.x + a3.y) + (a3.z + a3.w));
        if (tid < 128) xns_sm[r] = s;
        else           yns_sm[r] = s;
    }
    __syncthreads();

    // ---- warp tiling: warp (mw, nw) -> rows mw*32..+31, cols nw*32..+31 ----
    int mw = wid & 3;
    int nw = wid >> 2;

    uint32_t rA[2], mskA[2];
    #pragma unroll
    for (int mt = 0; mt < 2; mt++) {
        uint32_t row = mw * 32 + mt * 16 + (lane & 7) + ((lane >> 3) & 1) * 8;
        rA[mt] = row * 128;
        mskA[mt] = (rA[mt] >> 3) & 0x70;
    }
    uint32_t kA = (lane >> 4) * 16;
    uint32_t rB[2], mskB[2];
    #pragma unroll
    for (int np = 0; np < 2; np++) {
        uint32_t row = nw * 32 + np * 16 + (lane & 7) + ((lane >> 4) & 1) * 8;
        rB[np] = row * 128;
        mskB[np] = (rB[np] >> 3) & 0x70;
    }
    uint32_t kB = ((lane >> 3) & 1) * 16;

    float acc[2][4][4];
    #pragma unroll
    for (int mt = 0; mt < 2; mt++)
        #pragma unroll
        for (int nt = 0; nt < 4; nt++)
            #pragma unroll
            for (int q = 0; q < 4; q++) acc[mt][nt][q] = 0.f;

    // ---- mainloop: 4 kb panels ----
    #pragma unroll
    for (int kb = 0; kb < 4; kb++) {
        uint32_t kbyte = (uint32_t)kb * 32;
        uint32_t af[2][4], bfr[2][4];
        #pragma unroll
        for (int mt = 0; mt < 2; mt++)
            ldsm4(af[mt], sb + OFF_AXH + rA[mt] + ((kbyte + kA) ^ mskA[mt]));
        #pragma unroll
        for (int np = 0; np < 2; np++)
            ldsm4(bfr[np], sb + OFF_BYH + rB[np] + ((kbyte + kB) ^ mskB[np]));

        #pragma unroll
        for (int mt = 0; mt < 2; mt++)
            #pragma unroll
            for (int np = 0; np < 2; np++) {
                mma16816(acc[mt][2 * np],     af[mt], bfr[np][0], bfr[np][1]);
                mma16816(acc[mt][2 * np + 1], af[mt], bfr[np][2], bfr[np][3]);
            }
    }

    // ---- epilogue: out = xn + yn - 2*dot; permuted j -> STG.128 ----
    int g = lane >> 2;
    int tq = lane & 3;

    #pragma unroll
    for (int mt = 0; mt < 2; mt++) {
        int rlo = mw * 32 + mt * 16 + g;
        float xn_lo = xns_sm[rlo];
        float xn_hi = xns_sm[rlo + 8];
        float* out_lo = out + ((size_t)(b * NN + i0 + rlo)) * NN + j0;
        float* out_hi = out_lo + (size_t)8 * NN;
        #pragma unroll
        for (int q = 0; q < 2; q++) {
            int jl = nw * 32 + q * 16 + tq * 4;   // 4 consecutive logical j
            float4 yn = *(const float4*)(yns_sm + jl);
            float* aA = acc[mt][2 * q];       // physical block h=0 -> j+0, j+1
            float* aB = acc[mt][2 * q + 1];   // physical block h=1 -> j+2, j+3
            float4 v;
            v.x = fmaf(-2.f, aA[0], xn_lo + yn.x);
            v.y = fmaf(-2.f, aA[1], xn_lo + yn.y);
            v.z = fmaf(-2.f, aB[0], xn_lo + yn.z);
            v.w = fmaf(-2.f, aB[1], xn_lo + yn.w);
            *(float4*)(out_lo + jl) = v;
            v.x = fmaf(-2.f, aA[2], xn_hi + yn.x);
            v.y = fmaf(-2.f, aA[3], xn_hi + yn.y);
            v.z = fmaf(-2.f, aB[2], xn_hi + yn.z);
            v.w = fmaf(-2.f, aB[3], xn_hi + yn.w);
            *(float4*)(out_hi + jl) = v;
        }
    }
}

extern "C" void kernel_launch(void* const* d_in, const int* in_sizes, int n_in,
                              void* d_out, int out_size) {
    const float* x = (const float*)d_in[0];
    const float* y = (const float*)d_in[1];
    float* out = (float*)d_out;

    cudaFuncSetAttribute(pd_kernel, cudaFuncAttributeMaxDynamicSharedMemorySize,
                         (int)SMEM_BYTES);

    dim3 grid(NN / TJ, NN / TI, BB);
    pd_kernel<<<grid, 256, SMEM_BYTES>>>(x, y, out);
}